// round 1
// baseline (speedup 1.0000x reference)
#include <cuda_runtime.h>

// Problem constants
#define B_ 32
#define L_ 512
#define D_ 512
#define S_ 8

// Scratch: P[b][k][i][e] = arg1[b,i,:] @ Mr[k]   (256 MiB, static device alloc)
__device__ float g_P[(size_t)B_ * S_ * L_ * D_];
// Per-row projections [B*L][S]
__device__ float g_G1[B_ * L_ * S_];
__device__ float g_G2[B_ * L_ * S_];
__device__ float g_S1[B_ * L_ * S_];
__device__ float g_S2[B_ * L_ * S_];

__device__ __forceinline__ float sigmoidf_(float x) {
    // MUFU EX2 + MUFU RCP path, ~2^-22 rel err
    return __fdividef(1.0f, 1.0f + __expf(-x));
}

// ---------------------------------------------------------------------------
// Kernel A: row projections G1,G2,S1,S2  [B*L, 8] each
// grid = B*L blocks, 256 threads (8 warps x 4 dot-products each)
// ---------------------------------------------------------------------------
__global__ __launch_bounds__(256) void proj_kernel(
    const float* __restrict__ arg1, const float* __restrict__ arg2,
    const float* __restrict__ Wg, const float* __restrict__ V) {
    int r = blockIdx.x;  // 0..B*L-1
    __shared__ float row1[D_], row2[D_];
    const float* a1 = arg1 + (size_t)r * D_;
    const float* a2 = arg2 + (size_t)r * D_;
    for (int d = threadIdx.x; d < D_; d += 256) {
        row1[d] = a1[d];
        row2[d] = a2[d];
    }
    __syncthreads();
    int w = threadIdx.x >> 5, lane = threadIdx.x & 31;
#pragma unroll
    for (int q = 0; q < 4; q++) {
        int o = w * 4 + q;      // 0..31
        int p = o >> 3;         // 0:G1 1:G2 2:S1 3:S2
        int s = o & 7;
        const float* W = (p < 2) ? Wg : V;
        const float* row = (p & 1) ? row2 : row1;
        int off = (p & 1) ? D_ : 0;
        float sum = 0.f;
#pragma unroll 4
        for (int d = lane; d < D_; d += 32)
            sum += row[d] * W[(off + d) * S_ + s];
#pragma unroll
        for (int m = 16; m; m >>= 1) sum += __shfl_xor_sync(0xffffffffu, sum, m);
        if (lane == 0) {
            float* dst = (p == 0) ? g_G1 : (p == 1) ? g_G2 : (p == 2) ? g_S1 : g_S2;
            dst[r * S_ + s] = sum;
        }
    }
}

// ---------------------------------------------------------------------------
// Kernel B: P[b,k,i,e] = sum_d arg1[b,i,d] * Mr[k,d,e]
// 8 GEMMs [16384 x 512 x 512]; 64x64x16 tile, 256 threads, 4x4 microtile
// grid = (Ntiles=8, Mtiles=256, k=8)
// ---------------------------------------------------------------------------
__global__ __launch_bounds__(256) void pmul_kernel(
    const float* __restrict__ arg1, const float* __restrict__ Mr) {
    const int k = blockIdx.z;
    const int mB = blockIdx.y;   // 64-row tile over B*L
    const int nB = blockIdx.x;   // 64-col tile over D
    __shared__ float As[16][64];
    __shared__ float Bs[16][64];
    const int tid = threadIdx.x;
    const int tm = tid >> 4, tn = tid & 15;
    float acc[4][4] = {};
    const float* Atile = arg1 + (size_t)mB * 64 * D_;
    const float* Btile = Mr + (size_t)k * D_ * D_ + nB * 64;
    const int mA = tid >> 2, dqA = (tid & 3) * 4;  // A tile load map
    const int dB = tid >> 4, cB = (tid & 15) * 4;  // B tile load map

    for (int d0 = 0; d0 < D_; d0 += 16) {
        float4 va = *(const float4*)(Atile + (size_t)mA * D_ + d0 + dqA);
        float4 vb = *(const float4*)(Btile + (size_t)(d0 + dB) * D_ + cB);
        __syncthreads();
        As[dqA + 0][mA] = va.x; As[dqA + 1][mA] = va.y;
        As[dqA + 2][mA] = va.z; As[dqA + 3][mA] = va.w;
        *(float4*)&Bs[dB][cB] = vb;
        __syncthreads();
#pragma unroll
        for (int kk = 0; kk < 16; kk++) {
            float4 a4 = *(const float4*)&As[kk][tm * 4];
            float4 b4 = *(const float4*)&Bs[kk][tn * 4];
            float a[4] = {a4.x, a4.y, a4.z, a4.w};
            float b[4] = {b4.x, b4.y, b4.z, b4.w};
#pragma unroll
            for (int i = 0; i < 4; i++)
#pragma unroll
                for (int j = 0; j < 4; j++) acc[i][j] += a[i] * b[j];
        }
    }
    const int m0 = mB * 64;
    const int bb = m0 >> 9;      // batch
    const int i0 = m0 & 511;     // row within batch
    float* Pout = g_P + ((size_t)(bb * S_ + k) * L_ + i0) * D_;
#pragma unroll
    for (int i = 0; i < 4; i++) {
        float4 v = make_float4(acc[i][0], acc[i][1], acc[i][2], acc[i][3]);
        *(float4*)&Pout[(size_t)(tm * 4 + i) * D_ + nB * 64 + tn * 4] = v;
    }
}

// ---------------------------------------------------------------------------
// Kernel C: per (b, i-tile, j-tile): loop k, bi_k = P_k @ arg2^T, fused
// gated epilogue, final sigmoid.  64x64 output tile, 256 threads, 4x4 micro.
// grid = (L/64=8, L/64=8, B=32)
// ---------------------------------------------------------------------------
__global__ __launch_bounds__(256) void score_kernel(
    const float* __restrict__ arg2,
    const float* __restrict__ Bg, const float* __restrict__ bvec,
    const float* __restrict__ U, float* __restrict__ out) {
    const int b = blockIdx.z;
    const int i0 = blockIdx.y * 64;
    const int j0 = blockIdx.x * 64;
    __shared__ float As[16][64];
    __shared__ float Bs[16][64];
    __shared__ float G1t[64 * 8], G2t[64 * 8], S1t[64 * 8], S2t[64 * 8];
    const int tid = threadIdx.x;
    const int tm = tid >> 4, tn = tid & 15;

    // stage projection tiles (contiguous copies)
    for (int t = tid; t < 64 * 8; t += 256) {
        G1t[t] = g_G1[(size_t)(b * L_ + i0) * S_ + t];
        G2t[t] = g_G2[(size_t)(b * L_ + j0) * S_ + t];
        S1t[t] = g_S1[(size_t)(b * L_ + i0) * S_ + t];
        S2t[t] = g_S2[(size_t)(b * L_ + j0) * S_ + t];
    }

    float partial[4][4] = {};
    const float* Btile = arg2 + ((size_t)b * L_ + j0) * D_;
    const int mA = tid >> 2, dqA = (tid & 3) * 4;

    for (int k = 0; k < S_; k++) {
        float acc[4][4] = {};
        const float* Atile = g_P + ((size_t)(b * S_ + k) * L_ + i0) * D_;
        for (int e0 = 0; e0 < D_; e0 += 16) {
            float4 va = *(const float4*)(Atile + (size_t)mA * D_ + e0 + dqA);
            float4 vb = *(const float4*)(Btile + (size_t)mA * D_ + e0 + dqA);
            __syncthreads();
            As[dqA + 0][mA] = va.x; As[dqA + 1][mA] = va.y;
            As[dqA + 2][mA] = va.z; As[dqA + 3][mA] = va.w;
            Bs[dqA + 0][mA] = vb.x; Bs[dqA + 1][mA] = vb.y;
            Bs[dqA + 2][mA] = vb.z; Bs[dqA + 3][mA] = vb.w;
            __syncthreads();
#pragma unroll
            for (int kk = 0; kk < 16; kk++) {
                float4 a4 = *(const float4*)&As[kk][tm * 4];
                float4 b4 = *(const float4*)&Bs[kk][tn * 4];
                float a[4] = {a4.x, a4.y, a4.z, a4.w};
                float bb4[4] = {b4.x, b4.y, b4.z, b4.w};
#pragma unroll
                for (int i = 0; i < 4; i++)
#pragma unroll
                    for (int j = 0; j < 4; j++) acc[i][j] += a[i] * bb4[j];
            }
        }
        // fused gating epilogue for this slice k
        float Uk = U[k], Bgk = Bg[k];
#pragma unroll
        for (int ii = 0; ii < 4; ii++) {
            float g1 = G1t[(tm * 4 + ii) * S_ + k];
            float s1 = S1t[(tm * 4 + ii) * S_ + k];
#pragma unroll
            for (int jj = 0; jj < 4; jj++) {
                float g2 = G2t[(tn * 4 + jj) * S_ + k];
                float s2 = S2t[(tn * 4 + jj) * S_ + k];
                float g = sigmoidf_(g1 + g2 + Bgk);
                float si = sigmoidf_(s1 + s2);
                // bi*g + si*(1-g) = g*(bi - si) + si
                partial[ii][jj] += Uk * (g * (acc[ii][jj] - si) + si);
            }
        }
    }

    float c0 = 0.f;
#pragma unroll
    for (int kk = 0; kk < S_; kk++) c0 += U[kk] * bvec[kk];

#pragma unroll
    for (int ii = 0; ii < 4; ii++) {
        int i = i0 + tm * 4 + ii;
        float4 v;
        v.x = sigmoidf_(partial[ii][0] + c0);
        v.y = sigmoidf_(partial[ii][1] + c0);
        v.z = sigmoidf_(partial[ii][2] + c0);
        v.w = sigmoidf_(partial[ii][3] + c0);
        *(float4*)&out[((size_t)b * L_ + i) * L_ + j0 + tn * 4] = v;
    }
}

// ---------------------------------------------------------------------------
extern "C" void kernel_launch(void* const* d_in, const int* in_sizes, int n_in,
                              void* d_out, int out_size) {
    const float* arg1 = (const float*)d_in[0];  // [B,L,D]
    const float* arg2 = (const float*)d_in[1];  // [B,L,D]
    const float* Wg   = (const float*)d_in[2];  // [2D,S]
    const float* Bg   = (const float*)d_in[3];  // [S]
    const float* Mr   = (const float*)d_in[4];  // [S,D,D]
    const float* V    = (const float*)d_in[5];  // [2D,S]
    const float* bvec = (const float*)d_in[6];  // [S]
    const float* U    = (const float*)d_in[7];  // [S]
    float* out = (float*)d_out;                 // [B,L,L]

    (void)in_sizes; (void)n_in; (void)out_size;

    proj_kernel<<<B_ * L_, 256>>>(arg1, arg2, Wg, V);
    pmul_kernel<<<dim3(D_ / 64, (B_ * L_) / 64, S_), 256>>>(arg1, Mr);
    score_kernel<<<dim3(L_ / 64, L_ / 64, B_), 256>>>(arg2, Bg, bvec, U, out);
}